// round 2
// baseline (speedup 1.0000x reference)
#include <cuda_runtime.h>
#include <cstdint>

#define NNODES 10000
#define NEDGES 160000
#define FDIM   512
#define NGRAPH 64
#define ODIM   128

// Scratch (device globals; no allocation allowed)
__device__ float g_buf1[NNODES * FDIM];
__device__ float g_buf2[NNODES * FDIM];
__device__ float g_deg[NNODES];
__device__ float g_pooled[NGRAPH * FDIM];

__device__ __forceinline__ int clampi(int v, int lo, int hi) {
    return v < lo ? lo : (v > hi ? hi : v);
}

// ---------------------------------------------------------------------------
// Degree / normalization
// ---------------------------------------------------------------------------
__global__ void deg_init_kernel(float* deg, int n) {
    int i = blockIdx.x * blockDim.x + threadIdx.x;
    if (i < n) deg[i] = 1.0f;  // self-loop
}

__global__ void deg_count_kernel(const int* __restrict__ dst, float* deg, int e) {
    int i = blockIdx.x * blockDim.x + threadIdx.x;
    if (i < e) atomicAdd(&deg[clampi(dst[i], 0, NNODES - 1)], 1.0f);
}

__global__ void dinv_kernel(float* deg, int n) {
    int i = blockIdx.x * blockDim.x + threadIdx.x;
    if (i < n) deg[i] = rsqrtf(deg[i]);   // deg >= 1 always
}

// ---------------------------------------------------------------------------
// SGEMM: C[M,N] = A[M,K] @ B[K,N]   (row-major)
// 64x64 block tile, 16 K-tile, 256 threads, 4x4 per thread
// ---------------------------------------------------------------------------
__global__ void sgemm_kernel(const float* __restrict__ A, const float* __restrict__ B,
                             float* __restrict__ C, int M, int N, int K) {
    const int BM = 64, BN = 64, BK = 16;
    __shared__ float As[BK][BM];
    __shared__ float Bs[BK][BN + 4];

    int tid = threadIdx.x;
    int bm = blockIdx.y * BM;
    int bn = blockIdx.x * BN;

    int arow = tid >> 2;            // 0..63
    int acol = (tid & 3) * 4;       // 0,4,8,12
    int brow = tid >> 4;            // 0..15
    int bcol = (tid & 15) * 4;      // 0..60

    int tx = tid & 15;              // col group
    int ty = tid >> 4;              // row group

    float acc[4][4] = {};

    for (int k0 = 0; k0 < K; k0 += BK) {
        int gr = bm + arow;
        float4 av = make_float4(0.f, 0.f, 0.f, 0.f);
        if (gr < M) av = *(const float4*)(A + (size_t)gr * K + k0 + acol);
        As[acol + 0][arow] = av.x;
        As[acol + 1][arow] = av.y;
        As[acol + 2][arow] = av.z;
        As[acol + 3][arow] = av.w;

        float4 bv = *(const float4*)(B + (size_t)(k0 + brow) * N + bn + bcol);
        Bs[brow][bcol + 0] = bv.x;
        Bs[brow][bcol + 1] = bv.y;
        Bs[brow][bcol + 2] = bv.z;
        Bs[brow][bcol + 3] = bv.w;

        __syncthreads();

#pragma unroll
        for (int k = 0; k < BK; k++) {
            float a[4], b[4];
#pragma unroll
            for (int i = 0; i < 4; i++) a[i] = As[k][ty * 4 + i];
#pragma unroll
            for (int j = 0; j < 4; j++) b[j] = Bs[k][tx * 4 + j];
#pragma unroll
            for (int i = 0; i < 4; i++)
#pragma unroll
                for (int j = 0; j < 4; j++) acc[i][j] += a[i] * b[j];
        }
        __syncthreads();
    }

#pragma unroll
    for (int i = 0; i < 4; i++) {
        int r = bm + ty * 4 + i;
        if (r < M) {
            float4 v = make_float4(acc[i][0], acc[i][1], acc[i][2], acc[i][3]);
            *(float4*)(C + (size_t)r * N + bn + tx * 4) = v;
        }
    }
}

// ---------------------------------------------------------------------------
// Aggregation: self-loop init  out[i,:] = h[i,:] * dinv[i]^2
// ---------------------------------------------------------------------------
__global__ void agg_init_kernel(const float* __restrict__ h, const float* __restrict__ dinv,
                                float* __restrict__ out) {
    int idx = blockIdx.x * blockDim.x + threadIdx.x;      // over N*F/4
    int total = NNODES * FDIM / 4;
    if (idx >= total) return;
    int node = idx / (FDIM / 4);
    float s = dinv[node];
    s = s * s;
    float4 v = ((const float4*)h)[idx];
    v.x *= s; v.y *= s; v.z *= s; v.w *= s;
    ((float4*)out)[idx] = v;
}

// ---------------------------------------------------------------------------
// Edge aggregation: out[dst,:] += h[src,:] * dinv[src]*dinv[dst]
// One warp per edge
// ---------------------------------------------------------------------------
__global__ void agg_edges_kernel(const float* __restrict__ h, const float* __restrict__ dinv,
                                 float* __restrict__ out,
                                 const int* __restrict__ src,
                                 const int* __restrict__ dst) {
    int warp = (blockIdx.x * blockDim.x + threadIdx.x) >> 5;
    int lane = threadIdx.x & 31;
    if (warp >= NEDGES) return;
    int s = clampi(src[warp], 0, NNODES - 1);
    int d = clampi(dst[warp], 0, NNODES - 1);
    float nrm = dinv[s] * dinv[d];
    const float4* hs = (const float4*)(h + (size_t)s * FDIM);
    float* od = out + (size_t)d * FDIM;
#pragma unroll
    for (int f = lane; f < FDIM / 4; f += 32) {
        float4 v = hs[f];
        atomicAdd(&od[f * 4 + 0], v.x * nrm);
        atomicAdd(&od[f * 4 + 1], v.y * nrm);
        atomicAdd(&od[f * 4 + 2], v.z * nrm);
        atomicAdd(&od[f * 4 + 3], v.w * nrm);
    }
}

// ---------------------------------------------------------------------------
// bias + relu in place
// ---------------------------------------------------------------------------
__global__ void bias_relu_kernel(float* __restrict__ h, const float* __restrict__ b) {
    int idx = blockIdx.x * blockDim.x + threadIdx.x;
    if (idx >= NNODES * FDIM) return;
    float v = h[idx] + b[idx & (FDIM - 1)];
    h[idx] = v > 0.f ? v : 0.f;
}

// ---------------------------------------------------------------------------
// Pooling
// ---------------------------------------------------------------------------
__global__ void zero_kernel(float* p, int n) {
    int i = blockIdx.x * blockDim.x + threadIdx.x;
    if (i < n) p[i] = 0.f;
}

__global__ void pool_kernel(const float* __restrict__ h, const int* __restrict__ batch,
                            float* __restrict__ pooled) {
    int idx = blockIdx.x * blockDim.x + threadIdx.x;
    if (idx >= NNODES * FDIM) return;
    int node = idx >> 9;               // /FDIM
    int f = idx & (FDIM - 1);
    int g = clampi(batch[node], 0, NGRAPH - 1);
    atomicAdd(&pooled[g * FDIM + f], h[idx]);
}

// ---------------------------------------------------------------------------
// Final small GEMM: out[64,128] = pooled[64,512] @ Wlin[512,128] + blin
// ---------------------------------------------------------------------------
__global__ void final_gemm_kernel(const float* __restrict__ pooled,
                                  const float* __restrict__ Wlin,
                                  const float* __restrict__ blin,
                                  float* __restrict__ out) {
    __shared__ float p[FDIM];
    int g = blockIdx.x;
    int o = threadIdx.x;   // 128
    for (int k = o; k < FDIM; k += ODIM) p[k] = pooled[g * FDIM + k];
    __syncthreads();
    float acc = blin[o];
#pragma unroll 8
    for (int k = 0; k < FDIM; k++) acc += p[k] * Wlin[k * ODIM + o];
    out[g * ODIM + o] = acc;
}

// ---------------------------------------------------------------------------
// Launch
// ---------------------------------------------------------------------------
extern "C" void kernel_launch(void* const* d_in, const int* in_sizes, int n_in,
                              void* d_out, int out_size) {
    const float* x    = (const float*)d_in[0];
    const float* W1   = (const float*)d_in[1];
    const float* b1   = (const float*)d_in[2];
    const float* W2   = (const float*)d_in[3];
    const float* b2   = (const float*)d_in[4];
    const float* Wlin = (const float*)d_in[5];
    const float* blin = (const float*)d_in[6];
    const int* edge_index = (const int*)d_in[7];   // harness maps int64 -> int32
    const int* batch      = (const int*)d_in[8];

    const int* src = edge_index;
    const int* dst = edge_index + NEDGES;

    float *buf1, *buf2, *deg, *pooled_scratch;
    cudaGetSymbolAddress((void**)&buf1, g_buf1);
    cudaGetSymbolAddress((void**)&buf2, g_buf2);
    cudaGetSymbolAddress((void**)&deg, g_deg);
    cudaGetSymbolAddress((void**)&pooled_scratch, g_pooled);

    // Output layout: if out_size covers both tensors, pooled goes first in
    // d_out; otherwise d_out holds only the final [64,128] output.
    float* pooled;
    float* out2;
    if (out_size >= NGRAPH * FDIM + NGRAPH * ODIM) {
        pooled = (float*)d_out;
        out2   = (float*)d_out + NGRAPH * FDIM;
    } else {
        pooled = pooled_scratch;
        out2   = (float*)d_out;
    }

    // 1. degree / dinv
    deg_init_kernel<<<(NNODES + 255) / 256, 256>>>(deg, NNODES);
    deg_count_kernel<<<(NEDGES + 255) / 256, 256>>>(dst, deg, NEDGES);
    dinv_kernel<<<(NNODES + 255) / 256, 256>>>(deg, NNODES);

    dim3 gemm_grid(FDIM / 64, (NNODES + 63) / 64);

    // Layer 1
    sgemm_kernel<<<gemm_grid, 256>>>(x, W1, buf1, NNODES, FDIM, FDIM);
    agg_init_kernel<<<(NNODES * FDIM / 4 + 255) / 256, 256>>>(buf1, deg, buf2);
    agg_edges_kernel<<<(NEDGES * 32 + 255) / 256, 256>>>(buf1, deg, buf2, src, dst);
    bias_relu_kernel<<<(NNODES * FDIM + 255) / 256, 256>>>(buf2, b1);

    // Layer 2
    sgemm_kernel<<<gemm_grid, 256>>>(buf2, W2, buf1, NNODES, FDIM, FDIM);
    agg_init_kernel<<<(NNODES * FDIM / 4 + 255) / 256, 256>>>(buf1, deg, buf2);
    agg_edges_kernel<<<(NEDGES * 32 + 255) / 256, 256>>>(buf1, deg, buf2, src, dst);
    bias_relu_kernel<<<(NNODES * FDIM + 255) / 256, 256>>>(buf2, b2);

    // Pooling
    zero_kernel<<<(NGRAPH * FDIM + 255) / 256, 256>>>(pooled, NGRAPH * FDIM);
    pool_kernel<<<(NNODES * FDIM + 255) / 256, 256>>>(buf2, batch, pooled);

    // Final linear
    final_gemm_kernel<<<NGRAPH, ODIM>>>(pooled, Wlin, blin, out2);
}

// round 4
// speedup vs baseline: 1.5869x; 1.5869x over previous
#include <cuda_runtime.h>
#include <cstdint>

#define NNODES 10000
#define NEDGES 160000
#define FDIM   512
#define NGRAPH 64
#define ODIM   128

// Scratch (device globals; no allocation allowed)
__device__ float g_buf1[NNODES * FDIM];
__device__ float g_buf2[NNODES * FDIM];
__device__ float g_dinv[NNODES];
__device__ int   g_cnt[NNODES];
__device__ int   g_rowptr[NNODES + 1];
__device__ int   g_cursor[NNODES];
__device__ int   g_esrc[NEDGES];
__device__ float g_pooled[NGRAPH * FDIM];

__device__ __forceinline__ int clampi(int v, int lo, int hi) {
    return v < lo ? lo : (v > hi ? hi : v);
}

// ---------------------------------------------------------------------------
// CSR build: count, scan, scatter
// ---------------------------------------------------------------------------
__global__ void zero_cnt_kernel(int* cnt, int n) {
    int i = blockIdx.x * blockDim.x + threadIdx.x;
    if (i < n) cnt[i] = 0;
}

__global__ void count_kernel(const int* __restrict__ dst, int* cnt, int e) {
    int i = blockIdx.x * blockDim.x + threadIdx.x;
    if (i < e) atomicAdd(&cnt[clampi(dst[i], 0, NNODES - 1)], 1);
}

__global__ void dinv_kernel(const int* __restrict__ cnt, float* dinv, int n) {
    int i = blockIdx.x * blockDim.x + threadIdx.x;
    if (i < n) dinv[i] = rsqrtf((float)(cnt[i] + 1));   // +1 self loop
}

// single-block exclusive scan over NNODES entries (1024 threads)
__global__ void scan_kernel(const int* __restrict__ cnt, int* rowptr, int* cursor) {
    __shared__ int sdata[1024];
    __shared__ int carry_s;
    int tid = threadIdx.x;
    if (tid == 0) carry_s = 0;
    __syncthreads();
    for (int base = 0; base < NNODES; base += 1024) {
        int idx = base + tid;
        int v = (idx < NNODES) ? cnt[idx] : 0;
        sdata[tid] = v;
        __syncthreads();
        // Hillis-Steele inclusive scan
        for (int off = 1; off < 1024; off <<= 1) {
            int t2 = (tid >= off) ? sdata[tid - off] : 0;
            __syncthreads();
            sdata[tid] += t2;
            __syncthreads();
        }
        int excl = sdata[tid] - v;
        int c = carry_s;
        if (idx < NNODES) {
            rowptr[idx] = c + excl;
            cursor[idx] = c + excl;
        }
        __syncthreads();
        if (tid == 1023) carry_s = c + sdata[1023];
        __syncthreads();
    }
    if (tid == 0) rowptr[NNODES] = carry_s;
}

__global__ void scatter_kernel(const int* __restrict__ src, const int* __restrict__ dst,
                               int* cursor, int* esrc, int e) {
    int i = blockIdx.x * blockDim.x + threadIdx.x;
    if (i >= e) return;
    int d = clampi(dst[i], 0, NNODES - 1);
    int s = clampi(src[i], 0, NNODES - 1);
    int pos = atomicAdd(&cursor[d], 1);
    if (pos >= 0 && pos < NEDGES) esrc[pos] = s;
}

// ---------------------------------------------------------------------------
// SGEMM: C[M,N] = A[M,K] @ B[K,N]   row-major
// 128x128 tile, BK=8, 256 threads (16x16), 8x8 per thread, double-buffered
// ---------------------------------------------------------------------------
__global__ void __launch_bounds__(256, 2)
sgemm_kernel(const float* __restrict__ A, const float* __restrict__ B,
             float* __restrict__ C, int M, int N, int K) {
    const int BM = 128, BN = 128, BK = 8;
    __shared__ float As[2][BK][BM];       // transposed
    __shared__ float Bs[2][BK][BN];

    int tid = threadIdx.x;
    int bm = blockIdx.y * BM;
    int bn = blockIdx.x * BN;

    // A load: 128 rows x 8 cols -> 256 float4; thread t: row t/2, col (t&1)*4
    int arow = tid >> 1;
    int acol = (tid & 1) * 4;
    // B load: 8 rows x 128 cols -> 256 float4; thread t: row t/32, col (t&31)*4
    int brow = tid >> 5;
    int bcol = (tid & 31) * 4;

    int ty = tid >> 4;    // 0..15
    int tx = tid & 15;    // 0..15

    float acc[8][8] = {};
    float4 a_reg, b_reg;

    int T = K / BK;

    // prefetch tile 0
    {
        int gr = bm + arow;
        a_reg = make_float4(0.f, 0.f, 0.f, 0.f);
        if (gr < M) a_reg = *(const float4*)(A + (size_t)gr * K + acol);
        b_reg = *(const float4*)(B + (size_t)brow * N + bn + bcol);
        As[0][acol + 0][arow] = a_reg.x;
        As[0][acol + 1][arow] = a_reg.y;
        As[0][acol + 2][arow] = a_reg.z;
        As[0][acol + 3][arow] = a_reg.w;
        *(float4*)&Bs[0][brow][bcol] = b_reg;
    }
    __syncthreads();

    for (int t = 0; t < T; t++) {
        int cur = t & 1;
        int nxt = cur ^ 1;
        if (t + 1 < T) {
            int k0 = (t + 1) * BK;
            int gr = bm + arow;
            a_reg = make_float4(0.f, 0.f, 0.f, 0.f);
            if (gr < M) a_reg = *(const float4*)(A + (size_t)gr * K + k0 + acol);
            b_reg = *(const float4*)(B + (size_t)(k0 + brow) * N + bn + bcol);
        }

#pragma unroll
        for (int k = 0; k < BK; k++) {
            float a[8], b[8];
            *(float4*)&a[0] = *(const float4*)&As[cur][k][ty * 8];
            *(float4*)&a[4] = *(const float4*)&As[cur][k][ty * 8 + 4];
            *(float4*)&b[0] = *(const float4*)&Bs[cur][k][tx * 8];
            *(float4*)&b[4] = *(const float4*)&Bs[cur][k][tx * 8 + 4];
#pragma unroll
            for (int i = 0; i < 8; i++)
#pragma unroll
                for (int j = 0; j < 8; j++) acc[i][j] += a[i] * b[j];
        }

        if (t + 1 < T) {
            As[nxt][acol + 0][arow] = a_reg.x;
            As[nxt][acol + 1][arow] = a_reg.y;
            As[nxt][acol + 2][arow] = a_reg.z;
            As[nxt][acol + 3][arow] = a_reg.w;
            *(float4*)&Bs[nxt][brow][bcol] = b_reg;
        }
        __syncthreads();
    }

#pragma unroll
    for (int i = 0; i < 8; i++) {
        int r = bm + ty * 8 + i;
        if (r < M) {
            *(float4*)(C + (size_t)r * N + bn + tx * 8)     =
                make_float4(acc[i][0], acc[i][1], acc[i][2], acc[i][3]);
            *(float4*)(C + (size_t)r * N + bn + tx * 8 + 4) =
                make_float4(acc[i][4], acc[i][5], acc[i][6], acc[i][7]);
        }
    }
}

// ---------------------------------------------------------------------------
// Fused aggregation: for node d,
//   out[d,:] = relu( bias + dinv[d]^2 * h[d,:] + sum_{e: dst=d} dinv[src]*dinv[d]*h[src,:] )
// one block (128 threads) per node; each thread owns a float4 of the row
// ---------------------------------------------------------------------------
__global__ void __launch_bounds__(128)
fused_agg_kernel(const float* __restrict__ h, const float* __restrict__ dinv,
                 const int* __restrict__ rowptr, const int* __restrict__ esrc,
                 const float* __restrict__ bias, float* __restrict__ out) {
    __shared__ int   s_src[128];
    __shared__ float s_nrm[128];

    int d = blockIdx.x;
    int tid = threadIdx.x;
    float dd = dinv[d];

    int beg = rowptr[d];
    int end = rowptr[d + 1];

    // self loop + bias
    float4 hv = ((const float4*)(h + (size_t)d * FDIM))[tid];
    float sdd = dd * dd;
    float4 acc;
    acc.x = hv.x * sdd; acc.y = hv.y * sdd; acc.z = hv.z * sdd; acc.w = hv.w * sdd;

    for (int start = beg; start < end; start += 128) {
        int m = min(128, end - start);
        if (tid < m) {
            int s = esrc[start + tid];
            s_src[tid] = s;
            s_nrm[tid] = dinv[s] * dd;
        }
        __syncthreads();
        for (int j = 0; j < m; j++) {
            int s = s_src[j];
            float nrm = s_nrm[j];
            float4 v = ((const float4*)(h + (size_t)s * FDIM))[tid];
            acc.x += v.x * nrm; acc.y += v.y * nrm;
            acc.z += v.z * nrm; acc.w += v.w * nrm;
        }
        __syncthreads();
    }

    float4 bv = ((const float4*)bias)[tid];
    acc.x = fmaxf(acc.x + bv.x, 0.f);
    acc.y = fmaxf(acc.y + bv.y, 0.f);
    acc.z = fmaxf(acc.z + bv.z, 0.f);
    acc.w = fmaxf(acc.w + bv.w, 0.f);
    ((float4*)(out + (size_t)d * FDIM))[tid] = acc;
}

// ---------------------------------------------------------------------------
// Pooling (batch is sorted): blocks over (node-chunk, feature-strip),
// register-accumulate, flush on graph change
// ---------------------------------------------------------------------------
__global__ void zero_pool_kernel(float* p, int n) {
    int i = blockIdx.x * blockDim.x + threadIdx.x;
    if (i < n) p[i] = 0.f;
}

__global__ void pool_kernel(const float* __restrict__ h, const int* __restrict__ batch,
                            float* __restrict__ pooled) {
    const int CHUNK = 64;
    int f = blockIdx.x * 128 + threadIdx.x;           // feature (4 strips of 128)
    int n0 = blockIdx.y * CHUNK;
    int n1 = min(n0 + CHUNK, NNODES);
    if (n0 >= NNODES) return;

    float acc = 0.f;
    int gprev = clampi(batch[n0], 0, NGRAPH - 1);
    for (int n = n0; n < n1; n++) {
        int g = clampi(batch[n], 0, NGRAPH - 1);
        if (g != gprev) {
            atomicAdd(&pooled[gprev * FDIM + f], acc);
            acc = 0.f;
            gprev = g;
        }
        acc += h[(size_t)n * FDIM + f];
    }
    atomicAdd(&pooled[gprev * FDIM + f], acc);
}

// ---------------------------------------------------------------------------
// Final small GEMM: out[64,128] = pooled[64,512] @ Wlin[512,128] + blin
// ---------------------------------------------------------------------------
__global__ void final_gemm_kernel(const float* __restrict__ pooled,
                                  const float* __restrict__ Wlin,
                                  const float* __restrict__ blin,
                                  float* __restrict__ out) {
    __shared__ float p[FDIM];
    int g = blockIdx.x;
    int o = threadIdx.x;   // 128
    for (int k = o; k < FDIM; k += ODIM) p[k] = pooled[g * FDIM + k];
    __syncthreads();
    float acc = blin[o];
#pragma unroll 8
    for (int k = 0; k < FDIM; k++) acc += p[k] * Wlin[k * ODIM + o];
    out[g * ODIM + o] = acc;
}

// ---------------------------------------------------------------------------
// Launch
// ---------------------------------------------------------------------------
extern "C" void kernel_launch(void* const* d_in, const int* in_sizes, int n_in,
                              void* d_out, int out_size) {
    const float* x    = (const float*)d_in[0];
    const float* W1   = (const float*)d_in[1];
    const float* b1   = (const float*)d_in[2];
    const float* W2   = (const float*)d_in[3];
    const float* b2   = (const float*)d_in[4];
    const float* Wlin = (const float*)d_in[5];
    const float* blin = (const float*)d_in[6];
    const int* edge_index = (const int*)d_in[7];   // harness maps int64 -> int32
    const int* batch      = (const int*)d_in[8];

    const int* src = edge_index;
    const int* dst = edge_index + NEDGES;

    float *buf1, *buf2, *dinv, *pooled_scratch;
    int *cnt, *rowptr, *cursor, *esrc;
    cudaGetSymbolAddress((void**)&buf1, g_buf1);
    cudaGetSymbolAddress((void**)&buf2, g_buf2);
    cudaGetSymbolAddress((void**)&dinv, g_dinv);
    cudaGetSymbolAddress((void**)&pooled_scratch, g_pooled);
    cudaGetSymbolAddress((void**)&cnt, g_cnt);
    cudaGetSymbolAddress((void**)&rowptr, g_rowptr);
    cudaGetSymbolAddress((void**)&cursor, g_cursor);
    cudaGetSymbolAddress((void**)&esrc, g_esrc);

    float* pooled;
    float* out2;
    if (out_size >= NGRAPH * FDIM + NGRAPH * ODIM) {
        pooled = (float*)d_out;
        out2   = (float*)d_out + NGRAPH * FDIM;
    } else {
        pooled = pooled_scratch;
        out2   = (float*)d_out;
    }

    // CSR build + normalization
    zero_cnt_kernel<<<(NNODES + 255) / 256, 256>>>(cnt, NNODES);
    count_kernel<<<(NEDGES + 255) / 256, 256>>>(dst, cnt, NEDGES);
    dinv_kernel<<<(NNODES + 255) / 256, 256>>>(cnt, dinv, NNODES);
    scan_kernel<<<1, 1024>>>(cnt, rowptr, cursor);
    scatter_kernel<<<(NEDGES + 255) / 256, 256>>>(src, dst, cursor, esrc, NEDGES);

    dim3 gemm_grid(FDIM / 128, (NNODES + 127) / 128);

    // Layer 1
    sgemm_kernel<<<gemm_grid, 256>>>(x, W1, buf1, NNODES, FDIM, FDIM);
    fused_agg_kernel<<<NNODES, 128>>>(buf1, dinv, rowptr, esrc, b1, buf2);

    // Layer 2
    sgemm_kernel<<<gemm_grid, 256>>>(buf2, W2, buf1, NNODES, FDIM, FDIM);
    fused_agg_kernel<<<NNODES, 128>>>(buf1, dinv, rowptr, esrc, b2, buf2);

    // Pooling
    zero_pool_kernel<<<(NGRAPH * FDIM + 255) / 256, 256>>>(pooled, NGRAPH * FDIM);
    {
        dim3 pg(FDIM / 128, (NNODES + 63) / 64);
        pool_kernel<<<pg, 128>>>(buf2, batch, pooled);
    }

    // Final linear
    final_gemm_kernel<<<NGRAPH, ODIM>>>(pooled, Wlin, blin, out2);
}

// round 5
// speedup vs baseline: 3.5071x; 2.2101x over previous
#include <cuda_runtime.h>
#include <cstdint>

#define NNODES 10000
#define NEDGES 160000
#define FDIM   512
#define NGRAPH 64
#define ODIM   128

// Scratch (device globals; no allocation allowed)
__device__ float g_buf1[NNODES * FDIM];
__device__ float g_buf2[NNODES * FDIM];
__device__ float g_dinv[NNODES];
__device__ int   g_cnt[NNODES];
__device__ int   g_rowptr[NNODES + 1];
__device__ int   g_cursor[NNODES];
__device__ int   g_esrc[NEDGES];
__device__ float g_pooled[NGRAPH * FDIM];

__device__ __forceinline__ int clampi(int v, int lo, int hi) {
    return v < lo ? lo : (v > hi ? hi : v);
}

__device__ __forceinline__ uint32_t f2tf32(float f) {
    uint32_t r;
    asm("cvt.rna.tf32.f32 %0, %1;" : "=r"(r) : "f"(f));
    return r;
}

__device__ __forceinline__ void mma_tf32(float* c, const uint32_t* a, const uint32_t* b) {
    asm volatile(
        "mma.sync.aligned.m16n8k8.row.col.f32.tf32.tf32.f32 "
        "{%0,%1,%2,%3}, {%4,%5,%6,%7}, {%8,%9}, {%0,%1,%2,%3};"
        : "+f"(c[0]), "+f"(c[1]), "+f"(c[2]), "+f"(c[3])
        : "r"(a[0]), "r"(a[1]), "r"(a[2]), "r"(a[3]), "r"(b[0]), "r"(b[1]));
}

// ---------------------------------------------------------------------------
// CSR build: count, scan, scatter
// ---------------------------------------------------------------------------
__global__ void zero_cnt_kernel(int* cnt, int n) {
    int i = blockIdx.x * blockDim.x + threadIdx.x;
    if (i < n) cnt[i] = 0;
}

__global__ void count_kernel(const int* __restrict__ dst, int* cnt, int e) {
    int i = blockIdx.x * blockDim.x + threadIdx.x;
    if (i < e) atomicAdd(&cnt[clampi(dst[i], 0, NNODES - 1)], 1);
}

__global__ void dinv_kernel(const int* __restrict__ cnt, float* dinv, int n) {
    int i = blockIdx.x * blockDim.x + threadIdx.x;
    if (i < n) dinv[i] = rsqrtf((float)(cnt[i] + 1));   // +1 self loop
}

// single-block exclusive scan, warp-shuffle based (1024 threads)
__global__ void scan_kernel(const int* __restrict__ cnt, int* rowptr, int* cursor) {
    __shared__ int warpsum[32];
    __shared__ int carry_s;
    int tid = threadIdx.x;
    int lane = tid & 31;
    int wid = tid >> 5;
    if (tid == 0) carry_s = 0;
    __syncthreads();
    for (int base = 0; base < NNODES; base += 1024) {
        int idx = base + tid;
        int v = (idx < NNODES) ? cnt[idx] : 0;
        // inclusive warp scan
        int s = v;
#pragma unroll
        for (int off = 1; off < 32; off <<= 1) {
            int t2 = __shfl_up_sync(0xffffffffu, s, off);
            if (lane >= off) s += t2;
        }
        if (lane == 31) warpsum[wid] = s;
        __syncthreads();
        if (wid == 0) {
            int ws = warpsum[lane];
            int t = ws;
#pragma unroll
            for (int off = 1; off < 32; off <<= 1) {
                int t2 = __shfl_up_sync(0xffffffffu, t, off);
                if (lane >= off) t += t2;
            }
            warpsum[lane] = t - ws;   // exclusive warp offsets
        }
        __syncthreads();
        int c = carry_s;
        int excl = c + warpsum[wid] + s - v;
        if (idx < NNODES) {
            rowptr[idx] = excl;
            cursor[idx] = excl;
        }
        __syncthreads();
        if (tid == 1023) carry_s = excl + v;
        __syncthreads();
    }
    if (tid == 0) rowptr[NNODES] = carry_s;
}

__global__ void scatter_kernel(const int* __restrict__ src, const int* __restrict__ dst,
                               int* cursor, int* esrc, int e) {
    int i = blockIdx.x * blockDim.x + threadIdx.x;
    if (i >= e) return;
    int d = clampi(dst[i], 0, NNODES - 1);
    int s = clampi(src[i], 0, NNODES - 1);
    int pos = atomicAdd(&cursor[d], 1);
    if (pos >= 0 && pos < NEDGES) esrc[pos] = s;
}

// ---------------------------------------------------------------------------
// tf32 tensor-core GEMM: C[M,512] = A[M,512] @ B[512,512], fp32 accum.
// 128x128 tile, BK=16, 256 threads = 8 warps (2x4), each warp 64x32,
// m16n8k8 mma, double-buffered smem, padded layouts (conflict-free).
// ---------------------------------------------------------------------------
__global__ void __launch_bounds__(256, 2)
tf32_gemm_kernel(const float* __restrict__ A, const float* __restrict__ B,
                 float* __restrict__ C, int M) {
    const int K = FDIM, N = FDIM, BK = 16;
    __shared__ uint32_t As[2][128][20];   // [m][k], pad 16->20
    __shared__ uint32_t Bs[2][16][132];   // [k][n], pad 128->132

    int tid = threadIdx.x;
    int lane = tid & 31;
    int wid = tid >> 5;
    int warp_m = wid >> 2;       // 0..1
    int warp_n = wid & 3;        // 0..3

    int bm = blockIdx.y * 128;
    int bn = blockIdx.x * 128;

    // global load mapping
    int a_r = tid >> 2;          // 0..63 (two row blocks: +0, +64)
    int a_c = (tid & 3) * 4;     // k col group
    int b_r = tid >> 5;          // 0..7  (two row blocks: +0, +8)
    int b_c = (tid & 31) * 4;    // n col group

    float acc[4][4][4] = {};
    float4 a_pre[2], b_pre[2];

    const int T = K / BK;        // 32

    // prefetch tile 0
#pragma unroll
    for (int h = 0; h < 2; h++) {
        int gr = bm + a_r + h * 64;
        a_pre[h] = make_float4(0.f, 0.f, 0.f, 0.f);
        if (gr < M) a_pre[h] = *(const float4*)(A + (size_t)gr * K + a_c);
        b_pre[h] = *(const float4*)(B + (size_t)(b_r + h * 8) * N + bn + b_c);
    }
#pragma unroll
    for (int h = 0; h < 2; h++) {
        As[0][a_r + h * 64][a_c + 0] = f2tf32(a_pre[h].x);
        As[0][a_r + h * 64][a_c + 1] = f2tf32(a_pre[h].y);
        As[0][a_r + h * 64][a_c + 2] = f2tf32(a_pre[h].z);
        As[0][a_r + h * 64][a_c + 3] = f2tf32(a_pre[h].w);
        Bs[0][b_r + h * 8][b_c + 0] = f2tf32(b_pre[h].x);
        Bs[0][b_r + h * 8][b_c + 1] = f2tf32(b_pre[h].y);
        Bs[0][b_r + h * 8][b_c + 2] = f2tf32(b_pre[h].z);
        Bs[0][b_r + h * 8][b_c + 3] = f2tf32(b_pre[h].w);
    }
    __syncthreads();

    int mrow = warp_m * 64 + (lane >> 2);
    int ncol = warp_n * 32 + (lane >> 2);
    int koff = lane & 3;

    for (int t = 0; t < T; t++) {
        int cur = t & 1;
        int nxt = cur ^ 1;
        if (t + 1 < T) {
            int k0 = (t + 1) * BK;
#pragma unroll
            for (int h = 0; h < 2; h++) {
                int gr = bm + a_r + h * 64;
                a_pre[h] = make_float4(0.f, 0.f, 0.f, 0.f);
                if (gr < M) a_pre[h] = *(const float4*)(A + (size_t)gr * K + k0 + a_c);
                b_pre[h] = *(const float4*)(B + (size_t)(k0 + b_r + h * 8) * N + bn + b_c);
            }
        }

#pragma unroll
        for (int ks = 0; ks < BK; ks += 8) {
            uint32_t af[4][4], bf[4][2];
#pragma unroll
            for (int mi = 0; mi < 4; mi++) {
                int r = mrow + mi * 16;
                af[mi][0] = As[cur][r][ks + koff];
                af[mi][1] = As[cur][r + 8][ks + koff];
                af[mi][2] = As[cur][r][ks + koff + 4];
                af[mi][3] = As[cur][r + 8][ks + koff + 4];
            }
#pragma unroll
            for (int ni = 0; ni < 4; ni++) {
                int c = ncol + ni * 8;
                bf[ni][0] = Bs[cur][ks + koff][c];
                bf[ni][1] = Bs[cur][ks + koff + 4][c];
            }
#pragma unroll
            for (int mi = 0; mi < 4; mi++)
#pragma unroll
                for (int ni = 0; ni < 4; ni++)
                    mma_tf32(acc[mi][ni], af[mi], bf[ni]);
        }

        if (t + 1 < T) {
#pragma unroll
            for (int h = 0; h < 2; h++) {
                As[nxt][a_r + h * 64][a_c + 0] = f2tf32(a_pre[h].x);
                As[nxt][a_r + h * 64][a_c + 1] = f2tf32(a_pre[h].y);
                As[nxt][a_r + h * 64][a_c + 2] = f2tf32(a_pre[h].z);
                As[nxt][a_r + h * 64][a_c + 3] = f2tf32(a_pre[h].w);
                Bs[nxt][b_r + h * 8][b_c + 0] = f2tf32(b_pre[h].x);
                Bs[nxt][b_r + h * 8][b_c + 1] = f2tf32(b_pre[h].y);
                Bs[nxt][b_r + h * 8][b_c + 2] = f2tf32(b_pre[h].z);
                Bs[nxt][b_r + h * 8][b_c + 3] = f2tf32(b_pre[h].w);
            }
        }
        __syncthreads();
    }

    // epilogue
    int col_in_frag = (lane & 3) * 2;
#pragma unroll
    for (int mi = 0; mi < 4; mi++) {
#pragma unroll
        for (int ni = 0; ni < 4; ni++) {
            int r0 = bm + warp_m * 64 + mi * 16 + (lane >> 2);
            int c0 = bn + warp_n * 32 + ni * 8 + col_in_frag;
            if (r0 < M)
                *(float2*)(C + (size_t)r0 * N + c0) = make_float2(acc[mi][ni][0], acc[mi][ni][1]);
            if (r0 + 8 < M)
                *(float2*)(C + (size_t)(r0 + 8) * N + c0) = make_float2(acc[mi][ni][2], acc[mi][ni][3]);
        }
    }
}

// ---------------------------------------------------------------------------
// Fused aggregation: for node d,
//   out[d,:] = relu( bias + dinv[d]^2 * h[d,:] + sum_{e: dst=d} dinv[src]*dinv[d]*h[src,:] )
// one block (128 threads) per node; each thread owns a float4 of the row
// ---------------------------------------------------------------------------
__global__ void __launch_bounds__(128)
fused_agg_kernel(const float* __restrict__ h, const float* __restrict__ dinv,
                 const int* __restrict__ rowptr, const int* __restrict__ esrc,
                 const float* __restrict__ bias, float* __restrict__ out) {
    __shared__ int   s_src[128];
    __shared__ float s_nrm[128];

    int d = blockIdx.x;
    int tid = threadIdx.x;
    float dd = dinv[d];

    int beg = rowptr[d];
    int end = rowptr[d + 1];

    // self loop + bias
    float4 hv = ((const float4*)(h + (size_t)d * FDIM))[tid];
    float sdd = dd * dd;
    float4 acc;
    acc.x = hv.x * sdd; acc.y = hv.y * sdd; acc.z = hv.z * sdd; acc.w = hv.w * sdd;

    for (int start = beg; start < end; start += 128) {
        int m = min(128, end - start);
        if (tid < m) {
            int s = esrc[start + tid];
            s_src[tid] = s;
            s_nrm[tid] = dinv[s] * dd;
        }
        __syncthreads();
        for (int j = 0; j < m; j++) {
            int s = s_src[j];
            float nrm = s_nrm[j];
            float4 v = ((const float4*)(h + (size_t)s * FDIM))[tid];
            acc.x += v.x * nrm; acc.y += v.y * nrm;
            acc.z += v.z * nrm; acc.w += v.w * nrm;
        }
        __syncthreads();
    }

    float4 bv = ((const float4*)bias)[tid];
    acc.x = fmaxf(acc.x + bv.x, 0.f);
    acc.y = fmaxf(acc.y + bv.y, 0.f);
    acc.z = fmaxf(acc.z + bv.z, 0.f);
    acc.w = fmaxf(acc.w + bv.w, 0.f);
    ((float4*)(out + (size_t)d * FDIM))[tid] = acc;
}

// ---------------------------------------------------------------------------
// Pooling (batch is sorted)
// ---------------------------------------------------------------------------
__global__ void zero_pool_kernel(float* p, int n) {
    int i = blockIdx.x * blockDim.x + threadIdx.x;
    if (i < n) p[i] = 0.f;
}

__global__ void pool_kernel(const float* __restrict__ h, const int* __restrict__ batch,
                            float* __restrict__ pooled) {
    const int CHUNK = 64;
    int f = blockIdx.x * 128 + threadIdx.x;
    int n0 = blockIdx.y * CHUNK;
    int n1 = min(n0 + CHUNK, NNODES);
    if (n0 >= NNODES) return;

    float acc = 0.f;
    int gprev = clampi(batch[n0], 0, NGRAPH - 1);
    for (int n = n0; n < n1; n++) {
        int g = clampi(batch[n], 0, NGRAPH - 1);
        if (g != gprev) {
            atomicAdd(&pooled[gprev * FDIM + f], acc);
            acc = 0.f;
            gprev = g;
        }
        acc += h[(size_t)n * FDIM + f];
    }
    atomicAdd(&pooled[gprev * FDIM + f], acc);
}

// ---------------------------------------------------------------------------
// Final small GEMM: out[64,128] = pooled[64,512] @ Wlin[512,128] + blin
// ---------------------------------------------------------------------------
__global__ void final_gemm_kernel(const float* __restrict__ pooled,
                                  const float* __restrict__ Wlin,
                                  const float* __restrict__ blin,
                                  float* __restrict__ out) {
    __shared__ float p[FDIM];
    int g = blockIdx.x;
    int o = threadIdx.x;   // 128
    for (int k = o; k < FDIM; k += ODIM) p[k] = pooled[g * FDIM + k];
    __syncthreads();
    float acc = blin[o];
#pragma unroll 8
    for (int k = 0; k < FDIM; k++) acc += p[k] * Wlin[k * ODIM + o];
    out[g * ODIM + o] = acc;
}

// ---------------------------------------------------------------------------
// Launch
// ---------------------------------------------------------------------------
extern "C" void kernel_launch(void* const* d_in, const int* in_sizes, int n_in,
                              void* d_out, int out_size) {
    const float* x    = (const float*)d_in[0];
    const float* W1   = (const float*)d_in[1];
    const float* b1   = (const float*)d_in[2];
    const float* W2   = (const float*)d_in[3];
    const float* b2   = (const float*)d_in[4];
    const float* Wlin = (const float*)d_in[5];
    const float* blin = (const float*)d_in[6];
    const int* edge_index = (const int*)d_in[7];   // harness maps int64 -> int32
    const int* batch      = (const int*)d_in[8];

    const int* src = edge_index;
    const int* dst = edge_index + NEDGES;

    float *buf1, *buf2, *dinv, *pooled_scratch;
    int *cnt, *rowptr, *cursor, *esrc;
    cudaGetSymbolAddress((void**)&buf1, g_buf1);
    cudaGetSymbolAddress((void**)&buf2, g_buf2);
    cudaGetSymbolAddress((void**)&dinv, g_dinv);
    cudaGetSymbolAddress((void**)&pooled_scratch, g_pooled);
    cudaGetSymbolAddress((void**)&cnt, g_cnt);
    cudaGetSymbolAddress((void**)&rowptr, g_rowptr);
    cudaGetSymbolAddress((void**)&cursor, g_cursor);
    cudaGetSymbolAddress((void**)&esrc, g_esrc);

    float* pooled;
    float* out2;
    if (out_size >= NGRAPH * FDIM + NGRAPH * ODIM) {
        pooled = (float*)d_out;
        out2   = (float*)d_out + NGRAPH * FDIM;
    } else {
        pooled = pooled_scratch;
        out2   = (float*)d_out;
    }

    // CSR build + normalization
    zero_cnt_kernel<<<(NNODES + 255) / 256, 256>>>(cnt, NNODES);
    count_kernel<<<(NEDGES + 255) / 256, 256>>>(dst, cnt, NEDGES);
    dinv_kernel<<<(NNODES + 255) / 256, 256>>>(cnt, dinv, NNODES);
    scan_kernel<<<1, 1024>>>(cnt, rowptr, cursor);
    scatter_kernel<<<(NEDGES + 255) / 256, 256>>>(src, dst, cursor, esrc, NEDGES);

    dim3 gemm_grid(FDIM / 128, (NNODES + 127) / 128);

    // Layer 1
    tf32_gemm_kernel<<<gemm_grid, 256>>>(x, W1, buf1, NNODES);
    fused_agg_kernel<<<NNODES, 128>>>(buf1, dinv, rowptr, esrc, b1, buf2);

    // Layer 2
    tf32_gemm_kernel<<<gemm_grid, 256>>>(buf2, W2, buf1, NNODES);
    fused_agg_kernel<<<NNODES, 128>>>(buf1, dinv, rowptr, esrc, b2, buf2);

    // Pooling
    zero_pool_kernel<<<(NGRAPH * FDIM + 255) / 256, 256>>>(pooled, NGRAPH * FDIM);
    {
        dim3 pg(FDIM / 128, (NNODES + 63) / 64);
        pool_kernel<<<pg, 128>>>(buf2, batch, pooled);
    }

    // Final linear
    final_gemm_kernel<<<NGRAPH, ODIM>>>(pooled, Wlin, blin, out2);
}